// round 11
// baseline (speedup 1.0000x reference)
#include <cuda_runtime.h>
#include <math.h>
#include <stdint.h>

#define HH 512
#define WW 512
#define BN 32
#define CN 3
#define HW (HH * WW)

// Scratch (allocation-free rule: __device__ globals)
__device__ float g_A[HW];          // L * 0.85
__device__ float g_Z[CN * HW];     // min(z1,z2) * 0.15

// ---------------------------------------------------------------------------
// Per-block fp32 closed-form homography + inverse. Cancellation-free.
// ---------------------------------------------------------------------------
__device__ __forceinline__ void solve_inline(int b, const float* __restrict__ dst_off,
                                             float M[9]) {
    float j0 = __ldg(dst_off + (b * 4 + 0) * 2 + 0), k0 = __ldg(dst_off + (b * 4 + 0) * 2 + 1);
    float j1 = __ldg(dst_off + (b * 4 + 1) * 2 + 0), k1 = __ldg(dst_off + (b * 4 + 1) * 2 + 1);
    float j2 = __ldg(dst_off + (b * 4 + 2) * 2 + 0), k2 = __ldg(dst_off + (b * 4 + 2) * 2 + 1);
    float j3 = __ldg(dst_off + (b * 4 + 3) * 2 + 0), k3 = __ldg(dst_off + (b * 4 + 3) * 2 + 1);

    // corners: u = (j0, 512+j1, 512+j2, j3), v = (k0, k1, 512+k2, 512+k3)
    float sx  = j0 - j1 + j2 - j3;                // bases cancel exactly
    float sy  = k0 - k1 + k2 - k3;
    float dx1 = (j1 - j2);                        // u1-u2
    float dx2 = -512.f + (j3 - j2);               // u3-u2
    float dy1 = -512.f + (k1 - k2);               // v1-v2
    float dy2 = (k3 - k2);                        // v3-v2
    float iden = 1.0f / (dx1 * dy2 - dx2 * dy1);
    float g = (sx * dy2 - dx2 * sy) * iden;
    float h = (dx1 * sy - sx * dy1) * iden;

    float u1 = 512.f + j1, u3 = j3;
    float v1 = k1, v3 = 512.f + k3;
    float a  = (512.f + (j1 - j0)) + g * u1;
    float bb = (j3 - j0) + h * u3;
    float c  = j0;
    float d  = (k1 - k0) + g * v1;
    float e  = (512.f + (k3 - k0)) + h * v3;
    float f  = k0;

    const float is = 1.0f / 511.0f;
    float m0 = a * is,  m1 = bb * is, m2 = c;
    float m3 = d * is,  m4 = e * is,  m5 = f;
    float m6 = g * is,  m7 = h * is,  m8 = 1.0f;

    float c00 =  (m4 * m8 - m5 * m7);
    float c01 = -(m3 * m8 - m5 * m6);
    float c02 =  (m3 * m7 - m4 * m6);
    float idet = 1.0f / (m0 * c00 + m1 * c01 + m2 * c02);

    M[0] = c00 * idet;
    M[1] = -(m1 * m8 - m2 * m7) * idet;
    M[2] =  (m1 * m5 - m2 * m4) * idet;
    M[3] = c01 * idet;
    M[4] =  (m0 * m8 - m2 * m6) * idet;
    M[5] = -(m0 * m5 - m2 * m3) * idet;
    M[6] = c02 * idet;
    M[7] = -(m0 * m7 - m1 * m6) * idet;
    M[8] =  (m0 * m4 - m1 * m3) * idet;
}

// ---------------------------------------------------------------------------
// Setup: light mask (x0.85) + moire (x0.15). 128 blocks x 256 thr, 8 px/thr,
// float4 stores -> single scheduling wave so the PDL trigger completes fast.
// ---------------------------------------------------------------------------
__global__ void __launch_bounds__(256) setup_kernel(const float* __restrict__ ab,
                                                    const float* __restrict__ centers,
                                                    const int* __restrict__ cflag,
                                                    const int* __restrict__ direction,
                                                    const int* __restrict__ light_xy,
                                                    const int* __restrict__ theta) {
    cudaTriggerProgrammaticLaunchCompletion();   // let main launch now

    int t = blockIdx.x * blockDim.x + threadIdx.x;   // 32768 threads
    int idx0 = t * 8;                                 // 8 consecutive pixels
    int i = idx0 >> 9;            // row (same for all 8: 8 | 512)
    int j0 = idx0 & 511;          // first col

    float a = ab[0], bb = ab[1];
    int cf = cflag[0];
    int dk = direction[0] - 1;
    float lx = (float)light_xy[0], ly = (float)light_xy[1];
    float iml = 0.f;
    if (cf != 0) {
        float d0 = sqrtf(lx * lx + ly * ly);
        float d1 = sqrtf((lx - 255.f) * (lx - 255.f) + ly * ly);
        float d2 = sqrtf(lx * lx + (ly - 255.f) * (ly - 255.f));
        float d3 = sqrtf((lx - 512.f) * (lx - 512.f) + (ly - 512.f) * (ly - 512.f));
        iml = 1.0f / fmaxf(fmaxf(d0, d1), fmaxf(d2, d3));
    }

    float c0x = centers[0], c0y = centers[1];
    float c1x = centers[2], c1y = centers[3];
    float c2x = centers[4], c2y = centers[5];
    float th0 = (float)theta[0] * 0.017453292519943295f;
    float th1 = (float)theta[1] * 0.017453292519943295f;
    float th2 = (float)theta[2] * 0.017453292519943295f;
    float ct0 = __cosf(th0), st0 = __sinf(th0);
    float ct1 = __cosf(th1), st1 = __sinf(th1);
    float ct2 = __cosf(th2), st2 = __sinf(th2);

    const float TWO_PI = 6.283185307179586f;
    float La[8], Z0[8], Z1[8], Z2[8];

    #pragma unroll
    for (int q = 0; q < 8; q++) {
        int j = j0 + q;
        float L;
        if (cf == 0) {
            int tt = (dk == 0) ? i : (dk == 1) ? j : (dk == 2) ? (HH - 1 - i) : (WW - 1 - j);
            L = -((bb - a) / (float)(HH - 1)) * ((float)tt - (float)WW) + a;
        } else {
            float dx = (float)i - lx, dy = (float)j - ly;
            L = sqrtf(dx * dx + dy * dy) * iml * (a - bb) + bb;
        }
        La[q] = L * 0.85f;

        float xg = (float)(i + 1), yg = (float)(j + 1);
        {
            float dx = xg - c0x, dy = yg - c0y;
            float dist = sqrtf(dx * dx + dy * dy);
            float f1 = dist - floorf(dist);
            float t2 = ct0 * xg + st0 * yg;
            float f2 = t2 - floorf(t2);
            float z1 = 0.5f + 0.5f * __cosf(TWO_PI * f1);
            float z2 = 0.5f + 0.5f * __cosf(TWO_PI * f2);
            Z0[q] = fminf(z1, z2) * 0.15f;
        }
        {
            float dx = xg - c1x, dy = yg - c1y;
            float dist = sqrtf(dx * dx + dy * dy);
            float f1 = dist - floorf(dist);
            float t2 = ct1 * xg + st1 * yg;
            float f2 = t2 - floorf(t2);
            float z1 = 0.5f + 0.5f * __cosf(TWO_PI * f1);
            float z2 = 0.5f + 0.5f * __cosf(TWO_PI * f2);
            Z1[q] = fminf(z1, z2) * 0.15f;
        }
        {
            float dx = xg - c2x, dy = yg - c2y;
            float dist = sqrtf(dx * dx + dy * dy);
            float f1 = dist - floorf(dist);
            float t2 = ct2 * xg + st2 * yg;
            float f2 = t2 - floorf(t2);
            float z1 = 0.5f + 0.5f * __cosf(TWO_PI * f1);
            float z2 = 0.5f + 0.5f * __cosf(TWO_PI * f2);
            Z2[q] = fminf(z1, z2) * 0.15f;
        }
    }

    #pragma unroll
    for (int h = 0; h < 2; h++) {
        int o = idx0 + h * 4;
        *(float4*)(g_A + o)          = make_float4(La[h*4], La[h*4+1], La[h*4+2], La[h*4+3]);
        *(float4*)(g_Z + o)          = make_float4(Z0[h*4], Z0[h*4+1], Z0[h*4+2], Z0[h*4+3]);
        *(float4*)(g_Z + HW + o)     = make_float4(Z1[h*4], Z1[h*4+1], Z1[h*4+2], Z1[h*4+3]);
        *(float4*)(g_Z + 2 * HW + o) = make_float4(Z2[h*4], Z2[h*4+1], Z2[h*4+2], Z2[h*4+3]);
    }
}

// ---------------------------------------------------------------------------
// Fused warp + blend. Block = 128 threads = one (b, y) row. Phase 1 is
// independent of setup; cudaGridDependencySynchronize gates only g_A/g_Z.
// Noise loads issue BEFORE the barrier so their latency hides under it.
// ---------------------------------------------------------------------------
__global__ void __launch_bounds__(128) main_kernel(const float* __restrict__ img,
                                                   const float* __restrict__ noise,
                                                   const float* __restrict__ dst_off,
                                                   float* __restrict__ out) {
    __shared__ float sres[3][WW];

    int b = blockIdx.z;
    int y = blockIdx.y;
    int tid = threadIdx.x;

    float M[9];
    solve_inline(b, dst_off, M);

    float fy = (float)y;
    float ftid = (float)tid;
    float nx = M[0] * ftid + (M[1] * fy + M[2]);
    float ny = M[3] * ftid + (M[4] * fy + M[5]);
    float nd = M[6] * ftid + (M[7] * fy + M[8]);
    const float sxs = M[0] * 128.f, sys = M[3] * 128.f, sds = M[6] * 128.f;
    const float* base = img + (size_t)b * (3 * HW);

    #pragma unroll
    for (int p = 0; p < 4; p++) {
        int x = p * 128 + tid;
        float inv = 1.0f / nd;
        float xs = nx * inv;
        float ys = ny * inv;
        nx += sxs; ny += sys; nd += sds;

        float xf = floorf(xs), yf = floorf(ys);
        float wx = xs - xf, wy = ys - yf;
        int ix = (int)xf, iy = (int)yf;
        bool vx0 = ((unsigned)ix < WW);
        bool vx1 = ((unsigned)(ix + 1) < WW);
        bool vy0 = ((unsigned)iy < HH);
        bool vy1 = ((unsigned)(iy + 1) < HH);
        bool p00 = vx0 && vy0, p01 = vx1 && vy0;
        bool p10 = vx0 && vy1, p11 = vx1 && vy1;
        float w00 = (1.f - wx) * (1.f - wy);
        float w01 = wx * (1.f - wy);
        float w10 = (1.f - wx) * wy;
        float w11 = wx * wy;
        int i00 = iy * WW + ix;   // raw; dereferenced only when predicate true

        #pragma unroll
        for (int ch = 0; ch < 3; ch++) {
            const float* pp = base + ch * HW + i00;
            float v00 = p00 ? __ldg(pp)          : 0.f;
            float v01 = p01 ? __ldg(pp + 1)      : 0.f;
            float v10 = p10 ? __ldg(pp + WW)     : 0.f;
            float v11 = p11 ? __ldg(pp + WW + 1) : 0.f;
            sres[ch][x] = v00 * w00 + v01 * w01 + v10 * w10 + v11 * w11;
        }
    }

    // noise loads issued BEFORE the barrier (independent of smem contents);
    // their DRAM latency overlaps barrier drain + grid-dependency wait.
    int x0 = tid * 4;
    size_t o0 = ((size_t)(b * 3 + 0) * HH + y) * WW + x0;
    size_t o1 = ((size_t)(b * 3 + 1) * HH + y) * WW + x0;
    size_t o2 = ((size_t)(b * 3 + 2) * HH + y) * WW + x0;
    float4 nv0 = __ldcs((const float4*)(noise + o0));
    float4 nv1 = __ldcs((const float4*)(noise + o1));
    float4 nv2 = __ldcs((const float4*)(noise + o2));

    __syncthreads();
    cudaGridDependencySynchronize();   // g_A / g_Z now visible

    const float kn = 0.031622776601683794f;  // sqrt(0.001)
    float4 av = *(const float4*)(g_A + (size_t)y * WW + x0);

    {
        float4 zv = *(const float4*)(g_Z + ((size_t)0 * HH + y) * WW + x0);
        float4 rv = *(const float4*)(&sres[0][x0]);
        float4 ov;
        ov.x = rv.x * av.x + zv.x + kn * nv0.x;
        ov.y = rv.y * av.y + zv.y + kn * nv0.y;
        ov.z = rv.z * av.z + zv.z + kn * nv0.z;
        ov.w = rv.w * av.w + zv.w + kn * nv0.w;
        __stcs((float4*)(out + o0), ov);
    }
    {
        float4 zv = *(const float4*)(g_Z + ((size_t)1 * HH + y) * WW + x0);
        float4 rv = *(const float4*)(&sres[1][x0]);
        float4 ov;
        ov.x = rv.x * av.x + zv.x + kn * nv1.x;
        ov.y = rv.y * av.y + zv.y + kn * nv1.y;
        ov.z = rv.z * av.z + zv.z + kn * nv1.z;
        ov.w = rv.w * av.w + zv.w + kn * nv1.w;
        __stcs((float4*)(out + o1), ov);
    }
    {
        float4 zv = *(const float4*)(g_Z + ((size_t)2 * HH + y) * WW + x0);
        float4 rv = *(const float4*)(&sres[2][x0]);
        float4 ov;
        ov.x = rv.x * av.x + zv.x + kn * nv2.x;
        ov.y = rv.y * av.y + zv.y + kn * nv2.y;
        ov.z = rv.z * av.z + zv.z + kn * nv2.z;
        ov.w = rv.w * av.w + zv.w + kn * nv2.w;
        __stcs((float4*)(out + o2), ov);
    }
}

// ---------------------------------------------------------------------------
extern "C" void kernel_launch(void* const* d_in, const int* in_sizes, int n_in,
                              void* d_out, int out_size) {
    const float* image    = (const float*)d_in[0];
    const float* dst_off  = (const float*)d_in[1];
    const float* ab       = (const float*)d_in[2];
    const float* centers  = (const float*)d_in[3];
    const float* noise    = (const float*)d_in[4];
    const int*   c        = (const int*)d_in[5];
    const int*   direction= (const int*)d_in[6];
    const int*   light_xy = (const int*)d_in[7];
    const int*   theta    = (const int*)d_in[8];
    float* out = (float*)d_out;

    setup_kernel<<<128, 256>>>(ab, centers, c, direction, light_xy, theta);

    cudaLaunchConfig_t cfg = {};
    cfg.gridDim = dim3(1, HH, BN);
    cfg.blockDim = dim3(128, 1, 1);
    cfg.dynamicSmemBytes = 0;
    cfg.stream = 0;
    cudaLaunchAttribute attr[1];
    attr[0].id = cudaLaunchAttributeProgrammaticStreamSerialization;
    attr[0].val.programmaticStreamSerializationAllowed = 1;
    cfg.attrs = attr;
    cfg.numAttrs = 1;
    cudaLaunchKernelEx(&cfg, main_kernel, image, noise, dst_off, out);
}

// round 12
// speedup vs baseline: 1.0483x; 1.0483x over previous
#include <cuda_runtime.h>
#include <math.h>
#include <stdint.h>

#define HH 512
#define WW 512
#define BN 32
#define CN 3
#define HW (HH * WW)

// Scratch (allocation-free rule: __device__ globals)
__device__ float g_A[HW];          // L * 0.85
__device__ float g_Z[CN * HW];     // min(z1,z2) * 0.15

// ---------------------------------------------------------------------------
// Per-block fp32 closed-form homography + inverse. Cancellation-free.
// ---------------------------------------------------------------------------
__device__ __forceinline__ void solve_inline(int b, const float* __restrict__ dst_off,
                                             float M[9]) {
    float j0 = __ldg(dst_off + (b * 4 + 0) * 2 + 0), k0 = __ldg(dst_off + (b * 4 + 0) * 2 + 1);
    float j1 = __ldg(dst_off + (b * 4 + 1) * 2 + 0), k1 = __ldg(dst_off + (b * 4 + 1) * 2 + 1);
    float j2 = __ldg(dst_off + (b * 4 + 2) * 2 + 0), k2 = __ldg(dst_off + (b * 4 + 2) * 2 + 1);
    float j3 = __ldg(dst_off + (b * 4 + 3) * 2 + 0), k3 = __ldg(dst_off + (b * 4 + 3) * 2 + 1);

    float sx  = j0 - j1 + j2 - j3;
    float sy  = k0 - k1 + k2 - k3;
    float dx1 = (j1 - j2);
    float dx2 = -512.f + (j3 - j2);
    float dy1 = -512.f + (k1 - k2);
    float dy2 = (k3 - k2);
    float iden = 1.0f / (dx1 * dy2 - dx2 * dy1);
    float g = (sx * dy2 - dx2 * sy) * iden;
    float h = (dx1 * sy - sx * dy1) * iden;

    float u1 = 512.f + j1, u3 = j3;
    float v1 = k1, v3 = 512.f + k3;
    float a  = (512.f + (j1 - j0)) + g * u1;
    float bb = (j3 - j0) + h * u3;
    float c  = j0;
    float d  = (k1 - k0) + g * v1;
    float e  = (512.f + (k3 - k0)) + h * v3;
    float f  = k0;

    const float is = 1.0f / 511.0f;
    float m0 = a * is,  m1 = bb * is, m2 = c;
    float m3 = d * is,  m4 = e * is,  m5 = f;
    float m6 = g * is,  m7 = h * is,  m8 = 1.0f;

    float c00 =  (m4 * m8 - m5 * m7);
    float c01 = -(m3 * m8 - m5 * m6);
    float c02 =  (m3 * m7 - m4 * m6);
    float idet = 1.0f / (m0 * c00 + m1 * c01 + m2 * c02);

    M[0] = c00 * idet;
    M[1] = -(m1 * m8 - m2 * m7) * idet;
    M[2] =  (m1 * m5 - m2 * m4) * idet;
    M[3] = c01 * idet;
    M[4] =  (m0 * m8 - m2 * m6) * idet;
    M[5] = -(m0 * m5 - m2 * m3) * idet;
    M[6] = c02 * idet;
    M[7] = -(m0 * m7 - m1 * m6) * idet;
    M[8] =  (m0 * m4 - m1 * m3) * idet;
}

// ---------------------------------------------------------------------------
// Setup (R10 form): light mask (x0.85) + moire (x0.15); PDL trigger at top.
// ---------------------------------------------------------------------------
__global__ void setup_kernel(const float* __restrict__ ab,
                             const float* __restrict__ centers,
                             const int* __restrict__ cflag,
                             const int* __restrict__ direction,
                             const int* __restrict__ light_xy,
                             const int* __restrict__ theta) {
    cudaTriggerProgrammaticLaunchCompletion();

    int idx = blockIdx.x * blockDim.x + threadIdx.x;
    int i = idx / WW;   // row
    int j = idx % WW;   // col

    float a = ab[0], bb = ab[1];
    float L;
    if (cflag[0] == 0) {
        int k = direction[0] - 1;
        int t = (k == 0) ? i : (k == 1) ? j : (k == 2) ? (HH - 1 - i) : (WW - 1 - j);
        L = -((bb - a) / (float)(HH - 1)) * ((float)t - (float)WW) + a;
    } else {
        float x = (float)light_xy[0], y = (float)light_xy[1];
        float d0 = sqrtf(x * x + y * y);
        float d1 = sqrtf((x - 255.f) * (x - 255.f) + y * y);
        float d2 = sqrtf(x * x + (y - 255.f) * (y - 255.f));
        float d3 = sqrtf((x - 512.f) * (x - 512.f) + (y - 512.f) * (y - 512.f));
        float ml = fmaxf(fmaxf(d0, d1), fmaxf(d2, d3));
        float dx = (float)i - x, dy = (float)j - y;
        float dist = sqrtf(dx * dx + dy * dy);
        L = dist / ml * (a - bb) + bb;
    }
    g_A[idx] = L * 0.85f;

    const float TWO_PI = 6.283185307179586f;
    float xg = (float)(i + 1), yg = (float)(j + 1);
    #pragma unroll
    for (int k = 0; k < 3; k++) {
        float cx = centers[k * 2 + 0], cy = centers[k * 2 + 1];
        float th = (float)theta[k] * 0.017453292519943295f;
        float cth = __cosf(th), sth = __sinf(th);
        float dx = xg - cx, dy = yg - cy;
        float dist = sqrtf(dx * dx + dy * dy);
        float f1 = dist - floorf(dist);
        float t2 = cth * xg + sth * yg;
        float f2 = t2 - floorf(t2);
        float z1 = 0.5f + 0.5f * __cosf(TWO_PI * f1);
        float z2 = 0.5f + 0.5f * __cosf(TWO_PI * f2);
        g_Z[k * HW + idx] = fminf(z1, z2) * 0.15f;
    }
}

// ---------------------------------------------------------------------------
// Fused warp + blend with PAIR-GATHER.
// Block = 128 threads = one (b, y) row. Thread t, iter p handles pixels
// x = p*256 + 2t and x+1. When the pair is source-adjacent (99.6% of lanes),
// the 8 column loads per channel collapse to 6 (a0,a1,a2 / b0,b1,b2) with
// exact zero-padding semantics; non-adjacent pairs take a predicated 4-load
// fallback for px1. Pair results stored as one STS.64.
// ---------------------------------------------------------------------------
__global__ void __launch_bounds__(128) main_kernel(const float* __restrict__ img,
                                                   const float* __restrict__ noise,
                                                   const float* __restrict__ dst_off,
                                                   float* __restrict__ out) {
    __shared__ float sres[3][WW];

    int b = blockIdx.z;
    int y = blockIdx.y;
    int tid = threadIdx.x;

    float M[9];
    solve_inline(b, dst_off, M);

    float fy = (float)y;
    float cA = M[1] * fy + M[2];
    float cB = M[4] * fy + M[5];
    float cC = M[7] * fy + M[8];
    const float* base = img + (size_t)b * (3 * HW);

    #pragma unroll
    for (int p = 0; p < 2; p++) {
        int x = p * 256 + 2 * tid;
        float fx0 = (float)x, fx1 = (float)(x + 1);

        float inv0 = 1.0f / (M[6] * fx0 + cC);
        float inv1 = 1.0f / (M[6] * fx1 + cC);
        float xs0 = (M[0] * fx0 + cA) * inv0;
        float ys0 = (M[3] * fx0 + cB) * inv0;
        float xs1 = (M[0] * fx1 + cA) * inv1;
        float ys1 = (M[3] * fx1 + cB) * inv1;

        float xf0 = floorf(xs0), yf0 = floorf(ys0);
        float xf1 = floorf(xs1), yf1 = floorf(ys1);
        float wx0 = xs0 - xf0, wy0 = ys0 - yf0;
        float wx1 = xs1 - xf1, wy1 = ys1 - yf1;
        int ix0 = (int)xf0, iy0 = (int)yf0;
        int ix1 = (int)xf1, iy1 = (int)yf1;

        bool adj = (iy1 == iy0) && (ix1 == ix0 + 1);

        bool vy0 = ((unsigned)iy0 < HH);
        bool vy1 = ((unsigned)(iy0 + 1) < HH);
        bool vxa = ((unsigned)ix0 < WW);
        bool vxb = ((unsigned)(ix0 + 1) < WW);
        bool vxc = ((unsigned)(ix0 + 2) < WW);

        // px0 weights
        float w000 = (1.f - wx0) * (1.f - wy0);
        float w010 = wx0 * (1.f - wy0);
        float w100 = (1.f - wx0) * wy0;
        float w110 = wx0 * wy0;
        // px1 weights
        float w001 = (1.f - wx1) * (1.f - wy1);
        float w011 = wx1 * (1.f - wy1);
        float w101 = (1.f - wx1) * wy1;
        float w111 = wx1 * wy1;

        int i0 = iy0 * WW + ix0;       // raw; only dereferenced under predicate
        int i1 = iy1 * WW + ix1;

        // px1 fallback predicates
        bool fvx0 = ((unsigned)ix1 < WW);
        bool fvx1 = ((unsigned)(ix1 + 1) < WW);
        bool fvy0 = ((unsigned)iy1 < HH);
        bool fvy1 = ((unsigned)(iy1 + 1) < HH);
        bool q00 = !adj && fvx0 && fvy0, q01 = !adj && fvx1 && fvy0;
        bool q10 = !adj && fvx0 && fvy1, q11 = !adj && fvx1 && fvy1;

        bool pa0 = vxa && vy0, pa1 = vxb && vy0, pa2 = vxc && vy0;
        bool pb0 = vxa && vy1, pb1 = vxb && vy1, pb2 = vxc && vy1;

        #pragma unroll
        for (int ch = 0; ch < 3; ch++) {
            const float* pp = base + ch * HW + i0;
            float a0 = pa0 ? __ldg(pp)          : 0.f;
            float a1 = pa1 ? __ldg(pp + 1)      : 0.f;
            float a2 = pa2 ? __ldg(pp + 2)      : 0.f;
            float b0 = pb0 ? __ldg(pp + WW)     : 0.f;
            float b1 = pb1 ? __ldg(pp + WW + 1) : 0.f;
            float b2 = pb2 ? __ldg(pp + WW + 2) : 0.f;

            float r0 = a0 * w000 + a1 * w010 + b0 * w100 + b1 * w110;

            float v00, v01, v10, v11;
            if (adj) {
                v00 = a1; v01 = a2; v10 = b1; v11 = b2;
            } else {
                const float* qq = base + ch * HW + i1;
                v00 = q00 ? __ldg(qq)          : 0.f;
                v01 = q01 ? __ldg(qq + 1)      : 0.f;
                v10 = q10 ? __ldg(qq + WW)     : 0.f;
                v11 = q11 ? __ldg(qq + WW + 1) : 0.f;
            }
            float r1 = v00 * w001 + v01 * w011 + v10 * w101 + v11 * w111;

            *(float2*)(&sres[ch][x]) = make_float2(r0, r1);   // x even -> STS.64
        }
    }

    // noise loads before the barrier: latency overlaps barrier + PDL wait
    int x0 = tid * 4;
    size_t o0 = ((size_t)(b * 3 + 0) * HH + y) * WW + x0;
    size_t o1 = ((size_t)(b * 3 + 1) * HH + y) * WW + x0;
    size_t o2 = ((size_t)(b * 3 + 2) * HH + y) * WW + x0;
    float4 nv0 = __ldcs((const float4*)(noise + o0));
    float4 nv1 = __ldcs((const float4*)(noise + o1));
    float4 nv2 = __ldcs((const float4*)(noise + o2));

    __syncthreads();
    cudaGridDependencySynchronize();   // g_A / g_Z now visible

    const float kn = 0.031622776601683794f;  // sqrt(0.001)
    float4 av = *(const float4*)(g_A + (size_t)y * WW + x0);

    {
        float4 zv = *(const float4*)(g_Z + ((size_t)0 * HH + y) * WW + x0);
        float4 rv = *(const float4*)(&sres[0][x0]);
        float4 ov;
        ov.x = rv.x * av.x + zv.x + kn * nv0.x;
        ov.y = rv.y * av.y + zv.y + kn * nv0.y;
        ov.z = rv.z * av.z + zv.z + kn * nv0.z;
        ov.w = rv.w * av.w + zv.w + kn * nv0.w;
        __stcs((float4*)(out + o0), ov);
    }
    {
        float4 zv = *(const float4*)(g_Z + ((size_t)1 * HH + y) * WW + x0);
        float4 rv = *(const float4*)(&sres[1][x0]);
        float4 ov;
        ov.x = rv.x * av.x + zv.x + kn * nv1.x;
        ov.y = rv.y * av.y + zv.y + kn * nv1.y;
        ov.z = rv.z * av.z + zv.z + kn * nv1.z;
        ov.w = rv.w * av.w + zv.w + kn * nv1.w;
        __stcs((float4*)(out + o1), ov);
    }
    {
        float4 zv = *(const float4*)(g_Z + ((size_t)2 * HH + y) * WW + x0);
        float4 rv = *(const float4*)(&sres[2][x0]);
        float4 ov;
        ov.x = rv.x * av.x + zv.x + kn * nv2.x;
        ov.y = rv.y * av.y + zv.y + kn * nv2.y;
        ov.z = rv.z * av.z + zv.z + kn * nv2.z;
        ov.w = rv.w * av.w + zv.w + kn * nv2.w;
        __stcs((float4*)(out + o2), ov);
    }
}

// ---------------------------------------------------------------------------
extern "C" void kernel_launch(void* const* d_in, const int* in_sizes, int n_in,
                              void* d_out, int out_size) {
    const float* image    = (const float*)d_in[0];
    const float* dst_off  = (const float*)d_in[1];
    const float* ab       = (const float*)d_in[2];
    const float* centers  = (const float*)d_in[3];
    const float* noise    = (const float*)d_in[4];
    const int*   c        = (const int*)d_in[5];
    const int*   direction= (const int*)d_in[6];
    const int*   light_xy = (const int*)d_in[7];
    const int*   theta    = (const int*)d_in[8];
    float* out = (float*)d_out;

    setup_kernel<<<HW / 256, 256>>>(ab, centers, c, direction, light_xy, theta);

    cudaLaunchConfig_t cfg = {};
    cfg.gridDim = dim3(1, HH, BN);
    cfg.blockDim = dim3(128, 1, 1);
    cfg.dynamicSmemBytes = 0;
    cfg.stream = 0;
    cudaLaunchAttribute attr[1];
    attr[0].id = cudaLaunchAttributeProgrammaticStreamSerialization;
    attr[0].val.programmaticStreamSerializationAllowed = 1;
    cfg.attrs = attr;
    cfg.numAttrs = 1;
    cudaLaunchKernelEx(&cfg, main_kernel, image, noise, dst_off, out);
}